// round 3
// baseline (speedup 1.0000x reference)
#include <cuda_runtime.h>
#include <cuda_bf16.h>

// Problem constants
#define B_    2048
#define CELL_ 512
#define K_    30
#define L_    1024
#define V_    80
#define P_    90      // 3*K
#define NWARP 10
#define THREADS (NWARP*32)   // 320

__global__ __launch_bounds__(THREADS)
void window_kernel(const float* __restrict__ x,
                   const float* __restrict__ kappa_old,
                   const float* __restrict__ oh,
                   const float* __restrict__ tlen,
                   const float* __restrict__ W,
                   const float* __restrict__ bias,
                   float* __restrict__ out)
{
    const int b    = blockIdx.x;
    const int tid  = threadIdx.x;
    const int lane = tid & 31;
    const int warp = tid >> 5;

    __shared__ float xs[CELL_];
    __shared__ float alpha_s[K_], beta_s[K_], kappa_s[K_];
    __shared__ float phi_s[L_ + 1];
    __shared__ float red[NWARP * V_];   // 3.2 KB

    // ---- load x row into smem ----
    const float* xrow = x + (size_t)b * CELL_;
    for (int i = tid; i < CELL_; i += THREADS) xs[i] = xrow[i];
    __syncthreads();

    // ---- params = exp(x @ W.T + bias); warp w handles p = w, w+10, ... ----
    for (int p = warp; p < P_; p += NWARP) {
        const float* Wr = W + (size_t)p * CELL_;
        float s = 0.f;
        #pragma unroll 4
        for (int c = lane; c < CELL_; c += 32) s += xs[c] * Wr[c];
        #pragma unroll
        for (int o = 16; o; o >>= 1) s += __shfl_xor_sync(0xffffffffu, s, o);
        if (lane == 0) {
            float v = __expf(s + bias[p]);
            if (p < K_) {
                alpha_s[p] = v;
            } else if (p < 2 * K_) {
                beta_s[p - K_] = v;
            } else {
                int kk = p - 2 * K_;
                float kap = kappa_old[(size_t)b * K_ + kk] + v;
                kappa_s[kk] = kap;
                out[(size_t)B_ * V_ + (size_t)b * K_ + kk] = kap;  // kappa output
            }
        }
    }
    __syncthreads();

    // ---- phi[l] = scale * sum_k alpha_k * exp(-beta_k * (kappa_k - l)^2) ----
    const float scale = (float)L_ / tlen[b];
    float* phi_out = out + (size_t)B_ * V_ + (size_t)B_ * K_ + (size_t)b * (L_ + 1);
    for (int l = tid; l <= L_; l += THREADS) {
        const float fl = (float)l;
        float s = 0.f;
        #pragma unroll
        for (int k = 0; k < K_; k++) {
            float d = kappa_s[k] - fl;
            s += alpha_s[k] * __expf(-beta_s[k] * d * d);
        }
        s *= scale;
        phi_s[l]   = s;
        phi_out[l] = s;
    }
    __syncthreads();

    // ---- w[v] = sum_{l<L} phi[l] * oh[b][l][v]; warp-per-l striping ----
    const float* ohb = oh + (size_t)b * L_ * V_;
    float a0 = 0.f, a1 = 0.f, a2 = 0.f;
    #pragma unroll 4
    for (int l = warp; l < L_; l += NWARP) {
        const float p = phi_s[l];
        const float* r = ohb + (size_t)l * V_;
        a0 += p * r[lane];
        a1 += p * r[32 + lane];
        if (lane < 16) a2 += p * r[64 + lane];
    }
    red[warp * V_ + lane]      = a0;
    red[warp * V_ + 32 + lane] = a1;
    if (lane < 16) red[warp * V_ + 64 + lane] = a2;
    __syncthreads();

    if (tid < V_) {
        float s = 0.f;
        #pragma unroll
        for (int w2 = 0; w2 < NWARP; w2++) s += red[w2 * V_ + tid];
        out[(size_t)b * V_ + tid] = s;   // w output
    }
}

extern "C" void kernel_launch(void* const* d_in, const int* in_sizes, int n_in,
                              void* d_out, int out_size)
{
    const float* x         = (const float*)d_in[0];   // [B, CELL]
    const float* kappa_old = (const float*)d_in[1];   // [B, K]
    const float* oh        = (const float*)d_in[2];   // [B, L, V]
    const float* tlen      = (const float*)d_in[3];   // [B, 1]
    const float* W         = (const float*)d_in[4];   // [3K, CELL]
    const float* bias      = (const float*)d_in[5];   // [3K]
    float* out             = (float*)d_out;           // [B*V | B*K | B*(L+1)]

    window_kernel<<<B_, THREADS>>>(x, kappa_old, oh, tlen, W, bias, out);
}

// round 4
// speedup vs baseline: 2.7373x; 2.7373x over previous
#include <cuda_runtime.h>
#include <cuda_bf16.h>

// Problem constants
#define B_    2048
#define CELL_ 512
#define K_    30
#define L_    1024
#define V_    80
#define P_    90      // 3*K
#define NWARP 8
#define THREADS (NWARP*32)   // 256

__global__ __launch_bounds__(THREADS, 4)
void window_kernel(const float* __restrict__ x,
                   const float* __restrict__ kappa_old,
                   const float* __restrict__ oh,
                   const float* __restrict__ tlen,
                   const float* __restrict__ W,
                   const float* __restrict__ bias,
                   float* __restrict__ out)
{
    const int b    = blockIdx.x;
    const int tid  = threadIdx.x;
    const int lane = tid & 31;
    const int warp = tid >> 5;

    __shared__ float  xs[CELL_];
    __shared__ float  alpha_s[K_], beta_s[K_], kappa_s[K_];
    __shared__ float  phi_s[L_ + 1];
    __shared__ float4 red[NWARP * 20];   // 8 warps x 20 float4 = 2.56 KB

    // ---- load x row into smem (vectorized) ----
    {
        const float4* xrow4 = (const float4*)(x + (size_t)b * CELL_);
        float4* xs4 = (float4*)xs;
        for (int i = tid; i < CELL_ / 4; i += THREADS) xs4[i] = xrow4[i];
    }
    __syncthreads();

    // ---- params = exp(x @ W.T + bias); warp w handles p = w, w+8, ... ----
    for (int p = warp; p < P_; p += NWARP) {
        const float4* Wr4 = (const float4*)(W + (size_t)p * CELL_);
        const float4* xs4 = (const float4*)xs;
        float s = 0.f;
        #pragma unroll
        for (int c = lane; c < CELL_ / 4; c += 32) {
            float4 wv = Wr4[c];
            float4 xv = xs4[c];
            s += wv.x * xv.x + wv.y * xv.y + wv.z * xv.z + wv.w * xv.w;
        }
        #pragma unroll
        for (int o = 16; o; o >>= 1) s += __shfl_xor_sync(0xffffffffu, s, o);
        if (lane == 0) {
            float v = __expf(s + bias[p]);
            if (p < K_) {
                alpha_s[p] = v;
            } else if (p < 2 * K_) {
                beta_s[p - K_] = v;
            } else {
                int kk = p - 2 * K_;
                float kap = kappa_old[(size_t)b * K_ + kk] + v;
                kappa_s[kk] = kap;
                out[(size_t)B_ * V_ + (size_t)b * K_ + kk] = kap;  // kappa output
            }
        }
    }
    __syncthreads();

    // ---- phi[l] = scale * sum_k alpha_k * exp(-beta_k*(kappa_k - l)^2) ----
    const float scale = (float)L_ / tlen[b];
    float* phi_out = out + (size_t)B_ * V_ + (size_t)B_ * K_ + (size_t)b * (L_ + 1);
    for (int l = tid; l <= L_; l += THREADS) {
        const float fl = (float)l;
        float s = 0.f;
        #pragma unroll
        for (int k = 0; k < K_; k++) {
            float d = kappa_s[k] - fl;
            s += alpha_s[k] * __expf(-beta_s[k] * d * d);
        }
        s *= scale;
        phi_s[l]   = s;
        phi_out[l] = s;
    }
    __syncthreads();

    // ---- w[v] = sum_{l<L} phi[l] * oh[b][l][v] ----
    // One row = 80 floats = 20 float4 (16B aligned). Lanes 0..19 of each warp
    // fetch a whole row as LDG.128; warp-strided over l, unrolled x4 with
    // front-batched independent loads for MLP.
    if (lane < 20) {
        const float4* base = (const float4*)(oh + (size_t)b * L_ * V_) + lane;
        float4 acc = make_float4(0.f, 0.f, 0.f, 0.f);
        // 1024 / (8 warps * 4 unroll) = 32 iterations, no remainder
        for (int l0 = warp; l0 < L_; l0 += NWARP * 4) {
            float4 r0 = base[(size_t)(l0            ) * 20];
            float4 r1 = base[(size_t)(l0 +     NWARP) * 20];
            float4 r2 = base[(size_t)(l0 + 2 * NWARP) * 20];
            float4 r3 = base[(size_t)(l0 + 3 * NWARP) * 20];
            float p0 = phi_s[l0];
            float p1 = phi_s[l0 +     NWARP];
            float p2 = phi_s[l0 + 2 * NWARP];
            float p3 = phi_s[l0 + 3 * NWARP];
            acc.x += p0 * r0.x; acc.y += p0 * r0.y; acc.z += p0 * r0.z; acc.w += p0 * r0.w;
            acc.x += p1 * r1.x; acc.y += p1 * r1.y; acc.z += p1 * r1.z; acc.w += p1 * r1.w;
            acc.x += p2 * r2.x; acc.y += p2 * r2.y; acc.z += p2 * r2.z; acc.w += p2 * r2.w;
            acc.x += p3 * r3.x; acc.y += p3 * r3.y; acc.z += p3 * r3.z; acc.w += p3 * r3.w;
        }
        red[warp * 20 + lane] = acc;
    }
    __syncthreads();

    // final cross-warp reduction: thread v (<80) sums scalar slot v of all warps
    if (tid < V_) {
        const float* red_f = (const float*)red;
        float s = 0.f;
        #pragma unroll
        for (int w2 = 0; w2 < NWARP; w2++) s += red_f[w2 * V_ + tid];
        out[(size_t)b * V_ + tid] = s;   // w output
    }
}

extern "C" void kernel_launch(void* const* d_in, const int* in_sizes, int n_in,
                              void* d_out, int out_size)
{
    const float* x         = (const float*)d_in[0];   // [B, CELL]
    const float* kappa_old = (const float*)d_in[1];   // [B, K]
    const float* oh        = (const float*)d_in[2];   // [B, L, V]
    const float* tlen      = (const float*)d_in[3];   // [B, 1]
    const float* W         = (const float*)d_in[4];   // [3K, CELL]
    const float* bias      = (const float*)d_in[5];   // [3K]
    float* out             = (float*)d_out;           // [B*V | B*K | B*(L+1)]

    window_kernel<<<B_, THREADS>>>(x, kappa_old, oh, tlen, W, bias, out);
}